// round 1
// baseline (speedup 1.0000x reference)
#include <cuda_runtime.h>

// GC_3D loss: BCE(mean) + 1 - (1/13) * sum_k [ sum(di_k*dt_k) / (sum(dt_k^2)+1e-5) ]
// Shapes: (4,1,128,192,192) f32, offsets canonicalized to forward-z set.

#define DIM_Z 128
#define DIM_Y 192
#define DIM_X 192
#define DIM_XY (DIM_X * DIM_Y)
#define NSUM 27  // 13*2 boundary sums + 1 bce sum

__device__ double g_sums[NSUM];

__global__ void gc3d_zero_kernel() {
    int i = threadIdx.x;
    if (i < NSUM) g_sums[i] = 0.0;
}

__global__ void __launch_bounds__(256) gc3d_main_kernel(
    const float* __restrict__ in, const float* __restrict__ tg, int n)
{
    // canonical offsets: 4 with dz=0, 9 with dz=1 (all dy,dx in {-1,0,1})
    const int dzs[13] = {0, 0, 0, 0,  1, 1, 1, 1, 1, 1, 1, 1, 1};
    const int dys[13] = {0, 1, 1, 1, -1,-1,-1, 0, 0, 0, 1, 1, 1};
    const int dxs[13] = {1,-1, 0, 1, -1, 0, 1,-1, 0, 1,-1, 0, 1};

    float acc[NSUM];
#pragma unroll
    for (int i = 0; i < NSUM; i++) acc[i] = 0.0f;

    const int stride = gridDim.x * blockDim.x;
    for (int idx = blockIdx.x * blockDim.x + threadIdx.x; idx < n; idx += stride) {
        const int x  = idx % DIM_X;
        const int t1 = idx / DIM_X;
        const int y  = t1 % DIM_Y;
        const int z  = (t1 / DIM_Y) % DIM_Z;   // batch dim excluded from neighbor validity

        const float ic = in[idx];
        const float tc = tg[idx];

        // BCE partial: t*log(i) + (1-t)*log(1-i)
        acc[26] += tc * __logf(ic) + (1.0f - tc) * __logf(1.0f - ic);

#pragma unroll
        for (int k = 0; k < 13; k++) {
            const int dz = dzs[k], dy = dys[k], dx = dxs[k];
            const bool ok = (z + dz < DIM_Z) &
                            ((unsigned)(y + dy) < (unsigned)DIM_Y) &
                            ((unsigned)(x + dx) < (unsigned)DIM_X);
            const int nidx = idx + dz * DIM_XY + dy * DIM_X + dx;
            float iN = ic, tN = tc;       // invalid neighbor -> zero diff
            if (ok) {
                iN = __ldg(in + nidx);
                tN = __ldg(tg + nidx);
            }
            const float di = iN - ic;
            const float dt = tN - tc;
            acc[2 * k]     += di * dt;
            acc[2 * k + 1] += dt * dt;
        }
    }

    // intra-warp butterfly reduction of all 27 partials
#pragma unroll
    for (int i = 0; i < NSUM; i++) {
        float v = acc[i];
#pragma unroll
        for (int o = 16; o > 0; o >>= 1) v += __shfl_xor_sync(0xFFFFFFFFu, v, o);
        acc[i] = v;
    }

    __shared__ float sh[8][NSUM];
    const int wid = threadIdx.x >> 5;
    const int lid = threadIdx.x & 31;
    if (lid == 0) {
#pragma unroll
        for (int i = 0; i < NSUM; i++) sh[wid][i] = acc[i];
    }
    __syncthreads();
    if (wid == 0 && lid < NSUM) {
        float v = 0.0f;
        const int nw = (blockDim.x + 31) >> 5;
        for (int w = 0; w < nw; w++) v += sh[w][lid];
        atomicAdd(&g_sums[lid], (double)v);
    }
}

__global__ void gc3d_finalize_kernel(float* out, double inv_n) {
    if (threadIdx.x == 0 && blockIdx.x == 0) {
        double accv = 0.0;
#pragma unroll
        for (int k = 0; k < 13; k++)
            accv += g_sums[2 * k] / (g_sums[2 * k + 1] + 1e-5);
        const double bce = -g_sums[26] * inv_n;           // mean with negation
        out[0] = (float)(bce + 1.0 - accv / 13.0);        // LMDA = 1
    }
}

extern "C" void kernel_launch(void* const* d_in, const int* in_sizes, int n_in,
                              void* d_out, int out_size)
{
    const float* in = (const float*)d_in[0];
    const float* tg = (const float*)d_in[1];
    float* out = (float*)d_out;
    const int n = in_sizes[0];

    gc3d_zero_kernel<<<1, 32>>>();

    const int threads = 256;
    int blocks = 148 * 16;  // grid-stride; ~31 voxels/thread
    const int maxb = (n + threads - 1) / threads;
    if (blocks > maxb) blocks = maxb;
    gc3d_main_kernel<<<blocks, threads>>>(in, tg, n);

    gc3d_finalize_kernel<<<1, 32>>>(out, 1.0 / (double)n);
}

// round 2
// speedup vs baseline: 1.9290x; 1.9290x over previous
#include <cuda_runtime.h>

// GC_3D loss: BCE(mean) + 1 - (1/13) * sum_k [ sum(di_k*dt_k) / (sum(dt_k^2)+1e-5) ]
// Shape (4,1,128,192,192) f32. Offsets canonicalized to forward-z set:
//   dz=0: (0,0,1),(0,1,-1),(0,1,0),(0,1,1)   dz=1: all 9 (dy,dx) in {-1,0,1}^2
// Strategy: float4 along x (6-float row windows), register z-marching (3 fresh
// rows/step), templated y-boundary path, load-free z=127 epilogue.

#define DX 192
#define DY 192
#define DZ 128
#define DXY (DX * DY)
#define NX4 48
#define NSUM 27

__device__ double g_sums[NSUM];

__global__ void gc3d_zero_kernel() {
    int i = threadIdx.x;
    if (i < NSUM) g_sums[i] = 0.0;
}

__device__ __forceinline__ void ldwin(const float* __restrict__ p,
                                      int o_m1, int o_p4, float w[6]) {
    float4 v = *reinterpret_cast<const float4*>(p);
    w[0] = __ldg(p + o_m1);
    w[1] = v.x; w[2] = v.y; w[3] = v.z; w[4] = v.w;
    w[5] = __ldg(p + o_p4);
}

// One (row, dx) offset: 4 diffs per array, dt scaled by per-element guard flags
// (flag 0 -> dt=0 -> both di*dt and dt*dt vanish). Literal 1.0f flags fold away.
#define ACCUM(WI, WT, J, G0, G1, G2, G3, D, Q) do {                         \
    float di0 = (WI)[(J)]   - cI0; float dt0 = ((WT)[(J)]   - cT0) * (G0);  \
    float di1 = (WI)[(J)+1] - cI1; float dt1 = ((WT)[(J)+1] - cT1) * (G1);  \
    float di2 = (WI)[(J)+2] - cI2; float dt2 = ((WT)[(J)+2] - cT2) * (G2);  \
    float di3 = (WI)[(J)+3] - cI3; float dt3 = ((WT)[(J)+3] - cT3) * (G3);  \
    D = fmaf(di0, dt0, D); D = fmaf(di1, dt1, D);                           \
    D = fmaf(di2, dt2, D); D = fmaf(di3, dt3, D);                           \
    Q = fmaf(dt0, dt0, Q); Q = fmaf(dt1, dt1, Q);                           \
    Q = fmaf(dt2, dt2, Q); Q = fmaf(dt3, dt3, Q);                           \
} while (0)

// All three dx offsets on one row. RF = row validity flag (compile-time 1.0f
// on the interior path).
#define ROW3(WI, WT, RF, K) do {                                            \
    ACCUM(WI, WT, 0, fxm*(RF), (RF), (RF), (RF), dot[(K)],   den[(K)]);     \
    ACCUM(WI, WT, 1, (RF), (RF), (RF), (RF),     dot[(K)+1], den[(K)+1]);   \
    ACCUM(WI, WT, 2, (RF), (RF), (RF), fxp*(RF), dot[(K)+2], den[(K)+2]);   \
} while (0)

template<bool YG>
__device__ __forceinline__ void gc3d_march(
    const float* __restrict__ in, const float* __restrict__ tg,
    int base, int nsteps, bool do_epi,
    int o_m1, int o_p4, int dUp, int dDn,
    float fxm, float fxp, float fym, float fyp,
    float* dot, float* den, float& bce)
{
    float CWi[6], CWt[6], UWi[6], UWt[6];      // carried: center row, y+1 row
    ldwin(in + base,       o_m1, o_p4, CWi);
    ldwin(tg + base,       o_m1, o_p4, CWt);
    ldwin(in + base + dUp, o_m1, o_p4, UWi);
    ldwin(tg + base + dUp, o_m1, o_p4, UWt);

    for (int s = 0; s < nsteps; ++s) {
        const int baseN = base + DXY;
        float NmI[6], NmT[6], NcI[6], NcT[6], NpI[6], NpT[6];
        ldwin(in + baseN + dDn, o_m1, o_p4, NmI);
        ldwin(tg + baseN + dDn, o_m1, o_p4, NmT);
        ldwin(in + baseN,       o_m1, o_p4, NcI);
        ldwin(tg + baseN,       o_m1, o_p4, NcT);
        ldwin(in + baseN + dUp, o_m1, o_p4, NpI);
        ldwin(tg + baseN + dUp, o_m1, o_p4, NpT);

        const float cI0 = CWi[1], cI1 = CWi[2], cI2 = CWi[3], cI3 = CWi[4];
        const float cT0 = CWt[1], cT1 = CWt[2], cT2 = CWt[3], cT3 = CWt[4];

        // BCE partials: t*log(i) + (1-t)*log(1-i) = l2 + t*(l1-l2)
        {
            float l1, l2;
            l1 = __logf(cI0); l2 = __logf(1.0f - cI0); bce += l2 + cT0 * (l1 - l2);
            l1 = __logf(cI1); l2 = __logf(1.0f - cI1); bce += l2 + cT1 * (l1 - l2);
            l1 = __logf(cI2); l2 = __logf(1.0f - cI2); bce += l2 + cT2 * (l1 - l2);
            l1 = __logf(cI3); l2 = __logf(1.0f - cI3); bce += l2 + cT3 * (l1 - l2);
        }

        // k0: (0,0,+1) on center row
        ACCUM(CWi, CWt, 2, 1.0f, 1.0f, 1.0f, fxp, dot[0], den[0]);
        // k1..3: (0,1,dx) on carried y+1 row
        ROW3(UWi, UWt, (YG ? fyp : 1.0f), 1);
        // k4..6: (1,-1,dx)
        ROW3(NmI, NmT, (YG ? fym : 1.0f), 4);
        // k7..9: (1,0,dx)
        ROW3(NcI, NcT, 1.0f, 7);
        // k10..12: (1,1,dx)
        ROW3(NpI, NpT, (YG ? fyp : 1.0f), 10);

#pragma unroll
        for (int j = 0; j < 6; ++j) {
            CWi[j] = NcI[j]; CWt[j] = NcT[j];
            UWi[j] = NpI[j]; UWt[j] = NpT[j];
        }
        base = baseN;
    }

    if (do_epi) {  // z = 127: only dz=0 offsets; no loads needed
        const float cI0 = CWi[1], cI1 = CWi[2], cI2 = CWi[3], cI3 = CWi[4];
        const float cT0 = CWt[1], cT1 = CWt[2], cT2 = CWt[3], cT3 = CWt[4];
        {
            float l1, l2;
            l1 = __logf(cI0); l2 = __logf(1.0f - cI0); bce += l2 + cT0 * (l1 - l2);
            l1 = __logf(cI1); l2 = __logf(1.0f - cI1); bce += l2 + cT1 * (l1 - l2);
            l1 = __logf(cI2); l2 = __logf(1.0f - cI2); bce += l2 + cT2 * (l1 - l2);
            l1 = __logf(cI3); l2 = __logf(1.0f - cI3); bce += l2 + cT3 * (l1 - l2);
        }
        ACCUM(CWi, CWt, 2, 1.0f, 1.0f, 1.0f, fxp, dot[0], den[0]);
        ROW3(UWi, UWt, (YG ? fyp : 1.0f), 1);
    }
}

__global__ void __launch_bounds__(128) gc3d_main_kernel(
    const float* __restrict__ in, const float* __restrict__ tg)
{
    const int tid = blockIdx.x * blockDim.x + threadIdx.x;   // 0..73727
    const int x4 = tid % NX4;
    const int y  = (tid / NX4) % DY;
    const int t2 = tid / (NX4 * DY);   // 0..7
    const int zc = t2 & 1;
    const int b  = t2 >> 1;
    const int z0 = zc * 64;

    int base = ((b * DZ + z0) * DY + y) * DX + x4 * 4;

    const int   o_m1 = (x4 == 0)       ? 0 : -1;
    const int   o_p4 = (x4 == NX4 - 1) ? 3 : 4;
    const float fxm  = (x4 == 0)       ? 0.0f : 1.0f;
    const float fxp  = (x4 == NX4 - 1) ? 0.0f : 1.0f;
    const int   dUp  = (y == DY - 1) ? 0 : DX;
    const int   dDn  = (y == 0)      ? 0 : -DX;
    const float fyp  = (y == DY - 1) ? 0.0f : 1.0f;
    const float fym  = (y == 0)      ? 0.0f : 1.0f;

    const int  nsteps = (zc == 1) ? 63 : 64;
    const bool do_epi = (zc == 1);

    float dot[13], den[13], bce = 0.0f;
#pragma unroll
    for (int k = 0; k < 13; ++k) { dot[k] = 0.0f; den[k] = 0.0f; }

    if (y == 0 || y == DY - 1)
        gc3d_march<true >(in, tg, base, nsteps, do_epi, o_m1, o_p4, dUp, dDn,
                          fxm, fxp, fym, fyp, dot, den, bce);
    else
        gc3d_march<false>(in, tg, base, nsteps, do_epi, o_m1, o_p4, dUp, dDn,
                          fxm, fxp, fym, fyp, dot, den, bce);

    // pack 27 partials, warp butterfly, block reduce, atomic into doubles
    float acc[NSUM];
#pragma unroll
    for (int k = 0; k < 13; ++k) { acc[k] = dot[k]; acc[13 + k] = den[k]; }
    acc[26] = bce;

#pragma unroll
    for (int i = 0; i < NSUM; ++i) {
        float v = acc[i];
#pragma unroll
        for (int o = 16; o > 0; o >>= 1) v += __shfl_xor_sync(0xFFFFFFFFu, v, o);
        acc[i] = v;
    }

    __shared__ float sh[4][NSUM];
    const int wid = threadIdx.x >> 5;
    const int lid = threadIdx.x & 31;
    if (lid == 0) {
#pragma unroll
        for (int i = 0; i < NSUM; ++i) sh[wid][i] = acc[i];
    }
    __syncthreads();
    if (wid == 0 && lid < NSUM) {
        float v = sh[0][lid] + sh[1][lid] + sh[2][lid] + sh[3][lid];
        atomicAdd(&g_sums[lid], (double)v);
    }
}

__global__ void gc3d_finalize_kernel(float* out, double inv_n) {
    if (threadIdx.x == 0 && blockIdx.x == 0) {
        double accv = 0.0;
#pragma unroll
        for (int k = 0; k < 13; ++k)
            accv += g_sums[k] / (g_sums[13 + k] + 1e-5);
        const double bce = -g_sums[26] * inv_n;
        out[0] = (float)(bce + 1.0 - accv / 13.0);
    }
}

extern "C" void kernel_launch(void* const* d_in, const int* in_sizes, int n_in,
                              void* d_out, int out_size)
{
    const float* in = (const float*)d_in[0];
    const float* tg = (const float*)d_in[1];
    float* out = (float*)d_out;
    const int n = in_sizes[0];   // 18874368

    gc3d_zero_kernel<<<1, 32>>>();
    gc3d_main_kernel<<<576, 128>>>(in, tg);   // 576*128 = 73728 columns-chunks
    gc3d_finalize_kernel<<<1, 32>>>(out, 1.0 / (double)n);
}

// round 3
// speedup vs baseline: 2.7430x; 1.4220x over previous
#include <cuda_runtime.h>

// GC_3D loss: BCE(mean) + 1 - (1/13) * sum_k [ sum(di_k*dt_k) / (sum(dt_k^2)+1e-5) ]
// Shape (4,1,128,192,192) f32. Offsets canonicalized to forward-z set:
//   dz=0: (0,0,1),(0,1,-1),(0,1,0),(0,1,1)   dz=1: all 9 (dy,dx) in {-1,0,1}^2
// R3: 4 z-chunks (2x occupancy), unroll-2 z-march (load hoisting / copy renaming),
//     BCE accumulated in log2 domain.

#define DX 192
#define DY 192
#define DZ 128
#define DXY (DX * DY)
#define NX4 48
#define NSUM 27
#define ZCHUNKS 4
#define ZSTEP (DZ / ZCHUNKS)   // 32

__device__ double g_sums[NSUM];

__global__ void gc3d_zero_kernel() {
    int i = threadIdx.x;
    if (i < NSUM) g_sums[i] = 0.0;
}

__device__ __forceinline__ void ldwin(const float* __restrict__ p,
                                      int o_m1, int o_p4, float w[6]) {
    float4 v = *reinterpret_cast<const float4*>(p);
    w[0] = __ldg(p + o_m1);
    w[1] = v.x; w[2] = v.y; w[3] = v.z; w[4] = v.w;
    w[5] = __ldg(p + o_p4);
}

// One (row, dx) offset: 4 diffs per array, dt scaled by per-element guard flags
// (flag 0 -> dt=0 -> both di*dt and dt*dt vanish). Literal 1.0f flags fold away.
#define ACCUM(WI, WT, J, G0, G1, G2, G3, D, Q) do {                         \
    float di0 = (WI)[(J)]   - cI0; float dt0 = ((WT)[(J)]   - cT0) * (G0);  \
    float di1 = (WI)[(J)+1] - cI1; float dt1 = ((WT)[(J)+1] - cT1) * (G1);  \
    float di2 = (WI)[(J)+2] - cI2; float dt2 = ((WT)[(J)+2] - cT2) * (G2);  \
    float di3 = (WI)[(J)+3] - cI3; float dt3 = ((WT)[(J)+3] - cT3) * (G3);  \
    D = fmaf(di0, dt0, D); D = fmaf(di1, dt1, D);                           \
    D = fmaf(di2, dt2, D); D = fmaf(di3, dt3, D);                           \
    Q = fmaf(dt0, dt0, Q); Q = fmaf(dt1, dt1, Q);                           \
    Q = fmaf(dt2, dt2, Q); Q = fmaf(dt3, dt3, Q);                           \
} while (0)

#define ROW3(WI, WT, RF, K) do {                                            \
    ACCUM(WI, WT, 0, fxm*(RF), (RF), (RF), (RF), dot[(K)],   den[(K)]);     \
    ACCUM(WI, WT, 1, (RF), (RF), (RF), (RF),     dot[(K)+1], den[(K)+1]);   \
    ACCUM(WI, WT, 2, (RF), (RF), (RF), fxp*(RF), dot[(K)+2], den[(K)+2]);   \
} while (0)

// BCE partial in log2 domain: lg2(1-i) + t*(lg2(i) - lg2(1-i))
#define BCE4(CI, CT) do {                                                   \
    float l1, l2;                                                           \
    l1 = __log2f(CI[1]); l2 = __log2f(1.0f - CI[1]); bce += l2 + CT[1]*(l1-l2); \
    l1 = __log2f(CI[2]); l2 = __log2f(1.0f - CI[2]); bce += l2 + CT[2]*(l1-l2); \
    l1 = __log2f(CI[3]); l2 = __log2f(1.0f - CI[3]); bce += l2 + CT[3]*(l1-l2); \
    l1 = __log2f(CI[4]); l2 = __log2f(1.0f - CI[4]); bce += l2 + CT[4]*(l1-l2); \
} while (0)

template<bool YG>
__device__ __forceinline__ void gc3d_march(
    const float* __restrict__ in, const float* __restrict__ tg,
    int base, int nsteps, bool do_epi,
    int o_m1, int o_p4, int dUp, int dDn,
    float fxm, float fxp, float fym, float fyp,
    float* dot, float* den, float& bce)
{
    float CWi[6], CWt[6], UWi[6], UWt[6];      // carried: center row, y+1 row
    ldwin(in + base,       o_m1, o_p4, CWi);
    ldwin(tg + base,       o_m1, o_p4, CWt);
    ldwin(in + base + dUp, o_m1, o_p4, UWi);
    ldwin(tg + base + dUp, o_m1, o_p4, UWt);

#pragma unroll 2
    for (int s = 0; s < nsteps; ++s) {
        const int baseN = base + DXY;
        float NmI[6], NmT[6], NcI[6], NcT[6], NpI[6], NpT[6];
        ldwin(in + baseN + dDn, o_m1, o_p4, NmI);
        ldwin(tg + baseN + dDn, o_m1, o_p4, NmT);
        ldwin(in + baseN,       o_m1, o_p4, NcI);
        ldwin(tg + baseN,       o_m1, o_p4, NcT);
        ldwin(in + baseN + dUp, o_m1, o_p4, NpI);
        ldwin(tg + baseN + dUp, o_m1, o_p4, NpT);

        const float cI0 = CWi[1], cI1 = CWi[2], cI2 = CWi[3], cI3 = CWi[4];
        const float cT0 = CWt[1], cT1 = CWt[2], cT2 = CWt[3], cT3 = CWt[4];

        BCE4(CWi, CWt);

        // k0: (0,0,+1) on center row
        ACCUM(CWi, CWt, 2, 1.0f, 1.0f, 1.0f, fxp, dot[0], den[0]);
        // k1..3: (0,1,dx) on carried y+1 row
        ROW3(UWi, UWt, (YG ? fyp : 1.0f), 1);
        // k4..6: (1,-1,dx)
        ROW3(NmI, NmT, (YG ? fym : 1.0f), 4);
        // k7..9: (1,0,dx)
        ROW3(NcI, NcT, 1.0f, 7);
        // k10..12: (1,1,dx)
        ROW3(NpI, NpT, (YG ? fyp : 1.0f), 10);

#pragma unroll
        for (int j = 0; j < 6; ++j) {
            CWi[j] = NcI[j]; CWt[j] = NcT[j];
            UWi[j] = NpI[j]; UWt[j] = NpT[j];
        }
        base = baseN;
    }

    if (do_epi) {  // z = 127: only dz=0 offsets; no loads needed
        const float cI0 = CWi[1], cI1 = CWi[2], cI2 = CWi[3], cI3 = CWi[4];
        const float cT0 = CWt[1], cT1 = CWt[2], cT2 = CWt[3], cT3 = CWt[4];
        BCE4(CWi, CWt);
        ACCUM(CWi, CWt, 2, 1.0f, 1.0f, 1.0f, fxp, dot[0], den[0]);
        ROW3(UWi, UWt, (YG ? fyp : 1.0f), 1);
    }
}

__global__ void __launch_bounds__(128) gc3d_main_kernel(
    const float* __restrict__ in, const float* __restrict__ tg)
{
    const int tid = blockIdx.x * blockDim.x + threadIdx.x;   // 0..147455
    const int x4 = tid % NX4;
    const int y  = (tid / NX4) % DY;
    const int t2 = tid / (NX4 * DY);   // 0..15
    const int zc = t2 & 3;
    const int b  = t2 >> 2;
    const int z0 = zc * ZSTEP;

    int base = ((b * DZ + z0) * DY + y) * DX + x4 * 4;

    const int   o_m1 = (x4 == 0)       ? 0 : -1;
    const int   o_p4 = (x4 == NX4 - 1) ? 3 : 4;
    const float fxm  = (x4 == 0)       ? 0.0f : 1.0f;
    const float fxp  = (x4 == NX4 - 1) ? 0.0f : 1.0f;
    const int   dUp  = (y == DY - 1) ? 0 : DX;
    const int   dDn  = (y == 0)      ? 0 : -DX;
    const float fyp  = (y == DY - 1) ? 0.0f : 1.0f;
    const float fym  = (y == 0)      ? 0.0f : 1.0f;

    const int  nsteps = (zc == ZCHUNKS - 1) ? (ZSTEP - 1) : ZSTEP;
    const bool do_epi = (zc == ZCHUNKS - 1);

    float dot[13], den[13], bce = 0.0f;
#pragma unroll
    for (int k = 0; k < 13; ++k) { dot[k] = 0.0f; den[k] = 0.0f; }

    if (y == 0 || y == DY - 1)
        gc3d_march<true >(in, tg, base, nsteps, do_epi, o_m1, o_p4, dUp, dDn,
                          fxm, fxp, fym, fyp, dot, den, bce);
    else
        gc3d_march<false>(in, tg, base, nsteps, do_epi, o_m1, o_p4, dUp, dDn,
                          fxm, fxp, fym, fyp, dot, den, bce);

    // pack 27 partials, warp butterfly, block reduce, atomic into doubles
    float acc[NSUM];
#pragma unroll
    for (int k = 0; k < 13; ++k) { acc[k] = dot[k]; acc[13 + k] = den[k]; }
    acc[26] = bce;

#pragma unroll
    for (int i = 0; i < NSUM; ++i) {
        float v = acc[i];
#pragma unroll
        for (int o = 16; o > 0; o >>= 1) v += __shfl_xor_sync(0xFFFFFFFFu, v, o);
        acc[i] = v;
    }

    __shared__ float sh[4][NSUM];
    const int wid = threadIdx.x >> 5;
    const int lid = threadIdx.x & 31;
    if (lid == 0) {
#pragma unroll
        for (int i = 0; i < NSUM; ++i) sh[wid][i] = acc[i];
    }
    __syncthreads();
    if (wid == 0 && lid < NSUM) {
        float v = sh[0][lid] + sh[1][lid] + sh[2][lid] + sh[3][lid];
        atomicAdd(&g_sums[lid], (double)v);
    }
}

__global__ void gc3d_finalize_kernel(float* out, double inv_n) {
    if (threadIdx.x == 0 && blockIdx.x == 0) {
        double accv = 0.0;
#pragma unroll
        for (int k = 0; k < 13; ++k)
            accv += g_sums[k] / (g_sums[13 + k] + 1e-5);
        // BCE sum is in log2 units; convert with ln(2)
        const double bce = -g_sums[26] * inv_n * 0.6931471805599453;
        out[0] = (float)(bce + 1.0 - accv / 13.0);
    }
}

extern "C" void kernel_launch(void* const* d_in, const int* in_sizes, int n_in,
                              void* d_out, int out_size)
{
    const float* in = (const float*)d_in[0];
    const float* tg = (const float*)d_in[1];
    float* out = (float*)d_out;
    const int n = in_sizes[0];   // 18874368

    gc3d_zero_kernel<<<1, 32>>>();
    gc3d_main_kernel<<<1152, 128>>>(in, tg);   // 1152*128 = 147456 column-chunks
    gc3d_finalize_kernel<<<1, 32>>>(out, 1.0 / (double)n);
}